// round 5
// baseline (speedup 1.0000x reference)
#include <cuda_runtime.h>
#include <cuda_bf16.h>
#include <cuda_fp16.h>
#include <cuda_fp8.h>
#include <cstdint>
#include <cstddef>

// Problem dims (fixed by the dataset)
#define MDIM 8192
#define KDIM 4096
#define NDIM 4096
#define QBLOCK 128
#define FP8_MAX_F 448.0f
#define KBLOCKS (KDIM / QBLOCK)   // 32

// GEMM tiling: CTA 64x128x32, 8 warps as 2(m) x 4(n), warp tile 32x32
#define BM 64
#define BN 128
#define BK 32
#define KTILES (KDIM / BK)        // 128
#define STAGES 4
#define LDA (BK + 8)              // 40 halves = 80B row stride, conflict-free
#define A_BYTES (BM * LDA * 2)    // 5120
#define B_BYTES (BN * LDA * 2)    // 10240
#define STAGE_BYTES (A_BYTES + B_BYTES)      // 15360
#define SMEM_DYN (STAGES * STAGE_BYTES)      // 61440

// Scratch (device globals; no runtime allocation):
// raw fp8 values held exactly in fp16 + activation scales
__device__ __align__(16) __half g_A[(size_t)MDIM * KDIM];   // 64 MB, [M][K]
__device__ __align__(16) __half g_B[(size_t)NDIM * KDIM];   // 32 MB, [N][K]
__device__ __align__(16) float  g_Sx[(size_t)MDIM * KBLOCKS]; // 1 MB, [M][Kb]

// ---------------------------------------------------------------------------
// helpers
// ---------------------------------------------------------------------------
__device__ __forceinline__ void cp_async16(uint32_t smem_dst, const void* gptr) {
    asm volatile("cp.async.cg.shared.global [%0], [%1], 16;"
                 :: "r"(smem_dst), "l"(gptr) : "memory");
}

__device__ __forceinline__ void ldmatrix_x4(uint32_t* r, uint32_t addr) {
    asm volatile("ldmatrix.sync.aligned.m8n8.x4.shared.b16 {%0,%1,%2,%3}, [%4];"
                 : "=r"(r[0]), "=r"(r[1]), "=r"(r[2]), "=r"(r[3])
                 : "r"(addr) : "memory");
}

__device__ __forceinline__ void ldmatrix_x2(uint32_t* r, uint32_t addr) {
    asm volatile("ldmatrix.sync.aligned.m8n8.x2.shared.b16 {%0,%1}, [%2];"
                 : "=r"(r[0]), "=r"(r[1]) : "r"(addr) : "memory");
}

__device__ __forceinline__ void mma_16816(float* c, const uint32_t* a,
                                          const uint32_t* b) {
    asm volatile(
        "mma.sync.aligned.m16n8k16.row.col.f32.f16.f16.f32 "
        "{%0,%1,%2,%3}, {%4,%5,%6,%7}, {%8,%9}, {%0,%1,%2,%3};"
        : "+f"(c[0]), "+f"(c[1]), "+f"(c[2]), "+f"(c[3])
        : "r"(a[0]), "r"(a[1]), "r"(a[2]), "r"(a[3]), "r"(b[0]), "r"(b[1]));
}

__device__ __forceinline__ __half fp8_round_raw(float v) {
    // e4m3 quantize (RN-even satfinite, matches ml_dtypes grid), hold raw in fp16
    __nv_fp8_storage_t f8 = __nv_cvt_float_to_fp8(v, __NV_SATFINITE, __NV_E4M3);
    __half_raw hr = __nv_cvt_fp8_to_halfraw(f8, __NV_E4M3);
    return __half(hr);
}

// ---------------------------------------------------------------------------
// Kernel 1: activation blockwise fp8 quantize (raw q in fp16) + scale
// one warp per 128-element block
// ---------------------------------------------------------------------------
__global__ void __launch_bounds__(256) quant_x_kernel(const float* __restrict__ x) {
    int wg = (blockIdx.x * blockDim.x + threadIdx.x) >> 5; // block index = m*32+kb
    int lane = threadIdx.x & 31;
    size_t base = (size_t)wg * QBLOCK;
    float4 v = reinterpret_cast<const float4*>(x + base)[lane];

    float amax = fmaxf(fmaxf(fabsf(v.x), fabsf(v.y)), fmaxf(fabsf(v.z), fabsf(v.w)));
    #pragma unroll
    for (int off = 16; off > 0; off >>= 1)
        amax = fmaxf(amax, __shfl_xor_sync(0xffffffffu, amax, off));
    float scale = fmaxf(amax, 1e-12f) / FP8_MAX_F;

    __half h[4];
    h[0] = fp8_round_raw(v.x / scale);
    h[1] = fp8_round_raw(v.y / scale);
    h[2] = fp8_round_raw(v.z / scale);
    h[3] = fp8_round_raw(v.w / scale);
    reinterpret_cast<uint2*>(g_A)[(size_t)wg * 32 + lane] = *(uint2*)h;

    if (lane == 0) g_Sx[wg] = scale;  // layout [m][kb] == linear wg
}

// ---------------------------------------------------------------------------
// Kernel 2: weight fp8 cast, raw values in fp16 (scales applied in GEMM)
// ---------------------------------------------------------------------------
__global__ void __launch_bounds__(256) quant_w_kernel(const float* __restrict__ w) {
    size_t i = ((size_t)blockIdx.x * blockDim.x + threadIdx.x) * 4;
    float4 v = *reinterpret_cast<const float4*>(w + i);
    __half h[4];
    h[0] = fp8_round_raw(v.x);
    h[1] = fp8_round_raw(v.y);
    h[2] = fp8_round_raw(v.z);
    h[3] = fp8_round_raw(v.w);
    reinterpret_cast<uint2*>(g_B)[i >> 2] = *(uint2*)h;
}

// ---------------------------------------------------------------------------
// Kernel 3: GEMM on raw fp8-in-fp16 values with per-128k-block f32 rescale
//   y[m,n] = sum_kb sx[m,kb]*sw[nb,kb]* sum_{k in kb} qa*qb  (exact in f32)
//   Output: float32 (bf16-rounded values upcast, matching reference compare)
// ---------------------------------------------------------------------------
__global__ void __launch_bounds__(256, 2) gemm_kernel(const float* __restrict__ wsinv,
                                                      const float* __restrict__ bias,
                                                      float* __restrict__ out) {
    extern __shared__ __half smem[];
    __shared__ float bias_s[BN];
    __shared__ float sw_s[KBLOCKS];
    __shared__ float sx_s[KBLOCKS * BM];  // [kb][m_local], 8KB

    const int tid = threadIdx.x;
    const int wid = tid >> 5;
    const int lane = tid & 31;
    const int warp_m = wid & 1;   // 0..1 -> m rows 32*warp_m
    const int warp_n = wid >> 1;  // 0..3 -> n cols 32*warp_n

    // n-major rasterization: consecutive CTAs share the A band, B stays in L2
    const int n_tile = blockIdx.x & ((NDIM / BN) - 1);
    const int m_tile = blockIdx.x >> 5;
    const int m0 = m_tile * BM;
    const int n0 = n_tile * BN;
    const int nb = n0 >> 7;       // weight n-block (BN == QBLOCK)

    if (tid < BN)
        bias_s[tid] = __bfloat162float(__float2bfloat16_rn(bias[n0 + tid]));
    if (tid < KBLOCKS)
        sw_s[tid] = wsinv[nb * KBLOCKS + tid];
    #pragma unroll
    for (int idx = tid; idx < KBLOCKS * BM; idx += 256) {
        int kb = idx >> 6, ml = idx & (BM - 1);
        sx_s[idx] = g_Sx[(size_t)(m0 + ml) * KBLOCKS + kb];
    }
    __syncthreads();

    const __half* Abase = g_A + (size_t)m0 * KDIM;
    const __half* Bbase = g_B + (size_t)n0 * KDIM;
    const uint32_t smem_u32 = (uint32_t)__cvta_generic_to_shared(smem);

    auto issue_stage = [&](int kt, int s) {
        const int k0 = kt * BK;
        uint32_t a_s = smem_u32 + s * STAGE_BYTES;
        uint32_t b_s = a_s + A_BYTES;
        {   // A: 64 rows x 4 chunks = 256 chunks
            int row = tid >> 2, col = (tid & 3) * 8;
            cp_async16(a_s + (row * LDA + col) * 2,
                       Abase + (size_t)row * KDIM + k0 + col);
        }
        #pragma unroll
        for (int j = 0; j < 2; j++) {  // B: 128 rows x 4 chunks = 512 chunks
            int c = tid + j * 256;
            int row = c >> 2, col = (c & 3) * 8;
            cp_async16(b_s + (row * LDA + col) * 2,
                       Bbase + (size_t)row * KDIM + k0 + col);
        }
        asm volatile("cp.async.commit_group;" ::: "memory");
    };

    float acc[2][4][4];   // raw q*q partial (current 128-k block)
    float acc2[2][4][4];  // rescaled running total
    #pragma unroll
    for (int mf = 0; mf < 2; mf++)
        #pragma unroll
        for (int nf = 0; nf < 4; nf++)
            #pragma unroll
            for (int j = 0; j < 4; j++) { acc[mf][nf][j] = 0.f; acc2[mf][nf][j] = 0.f; }

    #pragma unroll
    for (int s = 0; s < STAGES - 1; s++) issue_stage(s, s);

    const int qrow = lane >> 2;
    const int qcol = (lane & 3) * 2;

    for (int kt = 0; kt < KTILES; kt++) {
        if (kt < KTILES - (STAGES - 1))
            asm volatile("cp.async.wait_group %0;" :: "n"(STAGES - 2) : "memory");
        else
            asm volatile("cp.async.wait_group 0;" ::: "memory");
        __syncthreads();

        int nxt = kt + STAGES - 1;
        if (nxt < KTILES) issue_stage(nxt, nxt & (STAGES - 1));

        const int s = kt & (STAGES - 1);
        const uint32_t a_s = smem_u32 + s * STAGE_BYTES;
        const uint32_t b_s = a_s + A_BYTES;

        #pragma unroll
        for (int ks = 0; ks < BK / 16; ks++) {
            const int kh = ks * 16;
            uint32_t a[2][4], b[4][2];
            #pragma unroll
            for (int mf = 0; mf < 2; mf++) {
                int row = warp_m * 32 + mf * 16 + (lane & 15);
                int col = kh + (lane >> 4) * 8;
                ldmatrix_x4(a[mf], a_s + (row * LDA + col) * 2);
            }
            #pragma unroll
            for (int nf = 0; nf < 4; nf++) {
                int row = warp_n * 32 + nf * 8 + (lane & 7);
                int col = kh + ((lane >> 3) & 1) * 8;
                ldmatrix_x2(b[nf], b_s + (row * LDA + col) * 2);
            }
            #pragma unroll
            for (int mf = 0; mf < 2; mf++)
                #pragma unroll
                for (int nf = 0; nf < 4; nf++)
                    mma_16816(acc[mf][nf], a[mf], b[nf]);
        }

        if ((kt & 3) == 3) {  // finished one 128-k quant block: rescale exactly
            const int kb = kt >> 2;
            const float sw = sw_s[kb];
            #pragma unroll
            for (int mf = 0; mf < 2; mf++) {
                int r0 = warp_m * 32 + mf * 16 + qrow;
                float f0 = sw * sx_s[kb * BM + r0];
                float f1 = sw * sx_s[kb * BM + r0 + 8];
                #pragma unroll
                for (int nf = 0; nf < 4; nf++) {
                    acc2[mf][nf][0] += f0 * acc[mf][nf][0];
                    acc2[mf][nf][1] += f0 * acc[mf][nf][1];
                    acc2[mf][nf][2] += f1 * acc[mf][nf][2];
                    acc2[mf][nf][3] += f1 * acc[mf][nf][3];
                    acc[mf][nf][0] = 0.f; acc[mf][nf][1] = 0.f;
                    acc[mf][nf][2] = 0.f; acc[mf][nf][3] = 0.f;
                }
            }
        }
    }

    // Epilogue: bf16(y) + bf16(bias), f32 add, round to bf16, upcast to f32
    #pragma unroll
    for (int mf = 0; mf < 2; mf++) {
        #pragma unroll
        for (int nf = 0; nf < 4; nf++) {
            int cn = warp_n * 32 + nf * 8 + qcol;
            float b0 = bias_s[cn], b1 = bias_s[cn + 1];
            #pragma unroll
            for (int half = 0; half < 2; half++) {
                int m = m0 + warp_m * 32 + mf * 16 + qrow + half * 8;
                float y0 = acc2[mf][nf][half * 2 + 0];
                float y1 = acc2[mf][nf][half * 2 + 1];
                float v0 = __bfloat162float(__float2bfloat16_rn(y0)) + b0;
                float v1 = __bfloat162float(__float2bfloat16_rn(y1)) + b1;
                float2 o;
                o.x = __bfloat162float(__float2bfloat16_rn(v0));
                o.y = __bfloat162float(__float2bfloat16_rn(v1));
                *reinterpret_cast<float2*>(out + (size_t)m * NDIM + n0 + cn) = o;
            }
        }
    }
}

// ---------------------------------------------------------------------------
// launch — inputs resolved by element count (robust to metadata ordering)
// ---------------------------------------------------------------------------
extern "C" void kernel_launch(void* const* d_in, const int* in_sizes, int n_in,
                              void* d_out, int out_size) {
    (void)out_size;
    const float *x = nullptr, *w = nullptr, *wsinv = nullptr, *bias = nullptr;
    for (int i = 0; i < n_in; i++) {
        switch (in_sizes[i]) {
            case MDIM * KDIM:                 x     = (const float*)d_in[i]; break; // 33554432
            case NDIM * KDIM:                 w     = (const float*)d_in[i]; break; // 16777216
            case (NDIM/QBLOCK)*(KDIM/QBLOCK): wsinv = (const float*)d_in[i]; break; // 1024
            case NDIM:                        bias  = (const float*)d_in[i]; break; // 4096
        }
    }
    float* out = (float*)d_out;

    {
        int nblocks = (MDIM * KBLOCKS) / 8; // 8 warps per CTA
        quant_x_kernel<<<nblocks, 256>>>(x);
    }
    {
        int nblocks = (NDIM * KDIM) / 4 / 256;
        quant_w_kernel<<<nblocks, 256>>>(w);
    }
    {
        cudaFuncSetAttribute(gemm_kernel,
                             cudaFuncAttributeMaxDynamicSharedMemorySize, SMEM_DYN);
        dim3 grid((MDIM / BM) * (NDIM / BN));  // 4096
        gemm_kernel<<<grid, 256, SMEM_DYN>>>(wsinv, bias, out);
    }
}

// round 6
// speedup vs baseline: 1.2222x; 1.2222x over previous
#include <cuda_runtime.h>
#include <cuda_bf16.h>
#include <cuda_fp16.h>
#include <cuda_fp8.h>
#include <cstdint>
#include <cstddef>

// Problem dims (fixed by the dataset)
#define MDIM 8192
#define KDIM 4096
#define NDIM 4096
#define QBLOCK 128
#define FP8_MAX_F 448.0f
#define KBLOCKS (KDIM / QBLOCK)   // 32

// GEMM tiling: CTA 64x128x64(fp8), 8 warps as 2(m) x 4(n), warp tile 32x32
#define BM 64
#define BN 128
#define BK 64
#define KTILES (KDIM / BK)        // 64
#define STAGES 4
#define LDAB 80                   // 64B fp8 row + 16B pad (conflict-free ldmatrix)
#define A_BYTES (BM * LDAB)       // 5120
#define B_BYTES (BN * LDAB)       // 10240
#define STAGE_BYTES (A_BYTES + B_BYTES)      // 15360
#define SMEM_DYN (STAGES * STAGE_BYTES)      // 61440

// Scratch (device globals; no runtime allocation):
// raw e4m3 bytes + activation scales
__device__ __align__(16) uint8_t g_A[(size_t)MDIM * KDIM];    // 32 MB, [M][K]
__device__ __align__(16) uint8_t g_B[(size_t)NDIM * KDIM];    // 16 MB, [N][K]
__device__ __align__(16) float   g_Sx[(size_t)MDIM * KBLOCKS]; // 1 MB, [M][Kb]

// ---------------------------------------------------------------------------
// helpers
// ---------------------------------------------------------------------------
__device__ __forceinline__ void cp_async16(uint32_t smem_dst, const void* gptr) {
    asm volatile("cp.async.cg.shared.global [%0], [%1], 16;"
                 :: "r"(smem_dst), "l"(gptr) : "memory");
}

__device__ __forceinline__ void ldmatrix_x4(uint32_t* r, uint32_t addr) {
    asm volatile("ldmatrix.sync.aligned.m8n8.x4.shared.b16 {%0,%1,%2,%3}, [%4];"
                 : "=r"(r[0]), "=r"(r[1]), "=r"(r[2]), "=r"(r[3])
                 : "r"(addr) : "memory");
}

__device__ __forceinline__ void ldmatrix_x2(uint32_t* r, uint32_t addr) {
    asm volatile("ldmatrix.sync.aligned.m8n8.x2.shared.b16 {%0,%1}, [%2];"
                 : "=r"(r[0]), "=r"(r[1]) : "r"(addr) : "memory");
}

// fp8 e4m3 MMA: m16n8k32, f32 accumulate (sm_89+ baseline feature)
__device__ __forceinline__ void mma_fp8(float* c, const uint32_t* a,
                                        const uint32_t* b) {
    asm volatile(
        "mma.sync.aligned.m16n8k32.row.col.f32.e4m3.e4m3.f32 "
        "{%0,%1,%2,%3}, {%4,%5,%6,%7}, {%8,%9}, {%0,%1,%2,%3};"
        : "+f"(c[0]), "+f"(c[1]), "+f"(c[2]), "+f"(c[3])
        : "r"(a[0]), "r"(a[1]), "r"(a[2]), "r"(a[3]), "r"(b[0]), "r"(b[1]));
}

__device__ __forceinline__ uint8_t fp8_byte(float v) {
    // e4m3 quantize (RN-even satfinite == ml_dtypes grid)
    return (uint8_t)__nv_cvt_float_to_fp8(v, __NV_SATFINITE, __NV_E4M3);
}

// ---------------------------------------------------------------------------
// Kernel 1: activation blockwise fp8 quantize (raw e4m3 bytes) + scale
// one warp per 128-element block
// ---------------------------------------------------------------------------
__global__ void __launch_bounds__(256) quant_x_kernel(const float* __restrict__ x) {
    int wg = (blockIdx.x * blockDim.x + threadIdx.x) >> 5; // block index = m*32+kb
    int lane = threadIdx.x & 31;
    size_t base = (size_t)wg * QBLOCK;
    float4 v = reinterpret_cast<const float4*>(x + base)[lane];

    float amax = fmaxf(fmaxf(fabsf(v.x), fabsf(v.y)), fmaxf(fabsf(v.z), fabsf(v.w)));
    #pragma unroll
    for (int off = 16; off > 0; off >>= 1)
        amax = fmaxf(amax, __shfl_xor_sync(0xffffffffu, amax, off));
    float scale = fmaxf(amax, 1e-12f) / FP8_MAX_F;
    float inv = 1.0f / scale;

    uint32_t p = (uint32_t)fp8_byte(v.x * inv) |
                 ((uint32_t)fp8_byte(v.y * inv) << 8) |
                 ((uint32_t)fp8_byte(v.z * inv) << 16) |
                 ((uint32_t)fp8_byte(v.w * inv) << 24);
    reinterpret_cast<uint32_t*>(g_A)[(size_t)wg * 32 + lane] = p;

    if (lane == 0) g_Sx[wg] = scale;  // layout [m][kb] == linear wg
}

// ---------------------------------------------------------------------------
// Kernel 2: weight fp8 cast (raw e4m3 bytes; scales applied in GEMM)
// ---------------------------------------------------------------------------
__global__ void __launch_bounds__(256) quant_w_kernel(const float* __restrict__ w) {
    size_t i = ((size_t)blockIdx.x * blockDim.x + threadIdx.x) * 4;
    float4 v = *reinterpret_cast<const float4*>(w + i);
    uint32_t p = (uint32_t)fp8_byte(v.x) |
                 ((uint32_t)fp8_byte(v.y) << 8) |
                 ((uint32_t)fp8_byte(v.z) << 16) |
                 ((uint32_t)fp8_byte(v.w) << 24);
    reinterpret_cast<uint32_t*>(g_B)[i >> 2] = p;
}

// ---------------------------------------------------------------------------
// Kernel 3: fp8 mma.sync GEMM with per-128k-block f32 rescale
//   y[m,n] = sum_kb sx[m,kb]*sw[nb,kb]* sum_{k in kb} qa*qb  (exact in f32)
//   Output: float32 (bf16-rounded values upcast, matching reference compare)
// ---------------------------------------------------------------------------
__global__ void __launch_bounds__(256, 2) gemm_kernel(const float* __restrict__ wsinv,
                                                      const float* __restrict__ bias,
                                                      float* __restrict__ out) {
    extern __shared__ uint8_t smem[];
    __shared__ float bias_s[BN];
    __shared__ float sw_s[KBLOCKS];
    __shared__ float sx_s[KBLOCKS * BM];  // [kb][m_local], 8KB

    const int tid = threadIdx.x;
    const int wid = tid >> 5;
    const int lane = tid & 31;
    const int warp_m = wid & 1;   // 0..1 -> m rows 32*warp_m
    const int warp_n = wid >> 1;  // 0..3 -> n cols 32*warp_n

    // n-major rasterization: consecutive CTAs share the A band, B stays in L2
    const int n_tile = blockIdx.x & ((NDIM / BN) - 1);
    const int m_tile = blockIdx.x >> 5;
    const int m0 = m_tile * BM;
    const int n0 = n_tile * BN;
    const int nb = n0 >> 7;       // weight n-block (BN == QBLOCK)

    if (tid < BN)
        bias_s[tid] = __bfloat162float(__float2bfloat16_rn(bias[n0 + tid]));
    if (tid < KBLOCKS)
        sw_s[tid] = wsinv[nb * KBLOCKS + tid];
    #pragma unroll
    for (int idx = tid; idx < KBLOCKS * BM; idx += 256) {
        int kb = idx >> 6, ml = idx & (BM - 1);
        sx_s[idx] = g_Sx[(size_t)(m0 + ml) * KBLOCKS + kb];
    }
    __syncthreads();

    const uint8_t* Abase = g_A + (size_t)m0 * KDIM;
    const uint8_t* Bbase = g_B + (size_t)n0 * KDIM;
    const uint32_t smem_u32 = (uint32_t)__cvta_generic_to_shared(smem);

    auto issue_stage = [&](int kt, int s) {
        const int k0 = kt * BK;
        uint32_t a_s = smem_u32 + s * STAGE_BYTES;
        uint32_t b_s = a_s + A_BYTES;
        {   // A: 64 rows x 4 x 16B chunks = 256 chunks
            int row = tid >> 2, c16 = (tid & 3) * 16;
            cp_async16(a_s + row * LDAB + c16,
                       Abase + (size_t)row * KDIM + k0 + c16);
        }
        #pragma unroll
        for (int j = 0; j < 2; j++) {  // B: 128 rows x 4 chunks = 512 chunks
            int c = tid + j * 256;
            int row = c >> 2, c16 = (c & 3) * 16;
            cp_async16(b_s + row * LDAB + c16,
                       Bbase + (size_t)row * KDIM + k0 + c16);
        }
        asm volatile("cp.async.commit_group;" ::: "memory");
    };

    float acc[2][4][4];   // raw q*q partial (current 128-k block)
    float acc2[2][4][4];  // rescaled running total
    #pragma unroll
    for (int mf = 0; mf < 2; mf++)
        #pragma unroll
        for (int nf = 0; nf < 4; nf++)
            #pragma unroll
            for (int j = 0; j < 4; j++) { acc[mf][nf][j] = 0.f; acc2[mf][nf][j] = 0.f; }

    #pragma unroll
    for (int s = 0; s < STAGES - 1; s++) issue_stage(s, s);

    const int qrow = lane >> 2;
    const int qcol = (lane & 3) * 2;

    for (int kt = 0; kt < KTILES; kt++) {
        if (kt < KTILES - (STAGES - 1))
            asm volatile("cp.async.wait_group %0;" :: "n"(STAGES - 2) : "memory");
        else
            asm volatile("cp.async.wait_group 0;" ::: "memory");
        __syncthreads();

        int nxt = kt + STAGES - 1;
        if (nxt < KTILES) issue_stage(nxt, nxt & (STAGES - 1));

        const int s = kt & (STAGES - 1);
        const uint32_t a_s = smem_u32 + s * STAGE_BYTES;
        const uint32_t b_s = a_s + A_BYTES;

        #pragma unroll
        for (int ks = 0; ks < 2; ks++) {   // two k32 steps per BK=64
            const int kbyte = ks * 32;
            uint32_t a[2][4], b[4][2];
            #pragma unroll
            for (int mf = 0; mf < 2; mf++) {
                int row = warp_m * 32 + mf * 16 + (lane & 15);
                int byte = kbyte + (lane >> 4) * 16;
                ldmatrix_x4(a[mf], a_s + row * LDAB + byte);
            }
            #pragma unroll
            for (int nf = 0; nf < 4; nf++) {
                int row = warp_n * 32 + nf * 8 + (lane & 7);
                int byte = kbyte + ((lane >> 3) & 1) * 16;
                ldmatrix_x2(b[nf], b_s + row * LDAB + byte);
            }
            #pragma unroll
            for (int mf = 0; mf < 2; mf++)
                #pragma unroll
                for (int nf = 0; nf < 4; nf++)
                    mma_fp8(acc[mf][nf], a[mf], b[nf]);
        }

        if (kt & 1) {  // finished one 128-k quant block: rescale exactly
            const int kb = kt >> 1;
            const float sw = sw_s[kb];
            #pragma unroll
            for (int mf = 0; mf < 2; mf++) {
                int r0 = warp_m * 32 + mf * 16 + qrow;
                float f0 = sw * sx_s[kb * BM + r0];
                float f1 = sw * sx_s[kb * BM + r0 + 8];
                #pragma unroll
                for (int nf = 0; nf < 4; nf++) {
                    acc2[mf][nf][0] += f0 * acc[mf][nf][0];
                    acc2[mf][nf][1] += f0 * acc[mf][nf][1];
                    acc2[mf][nf][2] += f1 * acc[mf][nf][2];
                    acc2[mf][nf][3] += f1 * acc[mf][nf][3];
                    acc[mf][nf][0] = 0.f; acc[mf][nf][1] = 0.f;
                    acc[mf][nf][2] = 0.f; acc[mf][nf][3] = 0.f;
                }
            }
        }
    }

    // Epilogue: bf16(y) + bf16(bias), f32 add, round to bf16, upcast to f32
    #pragma unroll
    for (int mf = 0; mf < 2; mf++) {
        #pragma unroll
        for (int nf = 0; nf < 4; nf++) {
            int cn = warp_n * 32 + nf * 8 + qcol;
            float b0 = bias_s[cn], b1 = bias_s[cn + 1];
            #pragma unroll
            for (int half = 0; half < 2; half++) {
                int m = m0 + warp_m * 32 + mf * 16 + qrow + half * 8;
                float y0 = acc2[mf][nf][half * 2 + 0];
                float y1 = acc2[mf][nf][half * 2 + 1];
                float v0 = __bfloat162float(__float2bfloat16_rn(y0)) + b0;
                float v1 = __bfloat162float(__float2bfloat16_rn(y1)) + b1;
                float2 o;
                o.x = __bfloat162float(__float2bfloat16_rn(v0));
                o.y = __bfloat162float(__float2bfloat16_rn(v1));
                *reinterpret_cast<float2*>(out + (size_t)m * NDIM + n0 + cn) = o;
            }
        }
    }
}

// ---------------------------------------------------------------------------
// launch — inputs resolved by element count (robust to metadata ordering)
// ---------------------------------------------------------------------------
extern "C" void kernel_launch(void* const* d_in, const int* in_sizes, int n_in,
                              void* d_out, int out_size) {
    (void)out_size;
    const float *x = nullptr, *w = nullptr, *wsinv = nullptr, *bias = nullptr;
    for (int i = 0; i < n_in; i++) {
        switch (in_sizes[i]) {
            case MDIM * KDIM:                 x     = (const float*)d_in[i]; break; // 33554432
            case NDIM * KDIM:                 w     = (const float*)d_in[i]; break; // 16777216
            case (NDIM/QBLOCK)*(KDIM/QBLOCK): wsinv = (const float*)d_in[i]; break; // 1024
            case NDIM:                        bias  = (const float*)d_in[i]; break; // 4096
        }
    }
    float* out = (float*)d_out;

    {
        int nblocks = (MDIM * KBLOCKS) / 8; // 8 warps per CTA
        quant_x_kernel<<<nblocks, 256>>>(x);
    }
    {
        int nblocks = (NDIM * KDIM) / 4 / 256;
        quant_w_kernel<<<nblocks, 256>>>(w);
    }
    {
        cudaFuncSetAttribute(gemm_kernel,
                             cudaFuncAttributeMaxDynamicSharedMemorySize, SMEM_DYN);
        dim3 grid((MDIM / BM) * (NDIM / BN));  // 4096
        gemm_kernel<<<grid, 256, SMEM_DYN>>>(wsinv, bias, out);
    }
}

// round 10
// speedup vs baseline: 1.3325x; 1.0903x over previous
#include <cuda_runtime.h>
#include <cuda_bf16.h>
#include <cuda_fp16.h>
#include <cuda_fp8.h>
#include <cstdint>
#include <cstddef>

// Problem dims (fixed by the dataset)
#define MDIM 8192
#define KDIM 4096
#define NDIM 4096
#define QBLOCK 128
#define FP8_MAX_F 448.0f
#define KBLOCKS (KDIM / QBLOCK)   // 32

// GEMM tiling: CTA 128x128x64(fp8), 8 warps as 2(m) x 4(n), warp tile 64x32
#define BM 128
#define BN 128
#define BK 64
#define KTILES (KDIM / BK)        // 64
#define STAGES 4
#define LDAB 80                   // 64B fp8 row + 16B pad (conflict-free ldmatrix)
#define A_BYTES (BM * LDAB)       // 10240
#define B_BYTES (BN * LDAB)       // 10240
#define STAGE_BYTES (A_BYTES + B_BYTES)      // 20480
#define SMEM_DYN (STAGES * STAGE_BYTES)      // 81920

// Scratch (device globals; no runtime allocation)
__device__ __align__(16) uint8_t g_A[(size_t)MDIM * KDIM];    // 32 MB, [M][K]
__device__ __align__(16) uint8_t g_B[(size_t)NDIM * KDIM];    // 16 MB, [N][K]
__device__ __align__(16) float   g_Sx[(size_t)MDIM * KBLOCKS]; // 1 MB, [M][Kb]

// ---------------------------------------------------------------------------
// helpers
// ---------------------------------------------------------------------------
__device__ __forceinline__ void cp_async16(uint32_t smem_dst, const void* gptr) {
    asm volatile("cp.async.cg.shared.global [%0], [%1], 16;"
                 :: "r"(smem_dst), "l"(gptr) : "memory");
}

__device__ __forceinline__ void ldmatrix_x4(uint32_t* r, uint32_t addr) {
    asm volatile("ldmatrix.sync.aligned.m8n8.x4.shared.b16 {%0,%1,%2,%3}, [%4];"
                 : "=r"(r[0]), "=r"(r[1]), "=r"(r[2]), "=r"(r[3])
                 : "r"(addr) : "memory");
}

// fp8 e4m3 MMA: m16n8k32, f32 accumulate (sm_89+ baseline feature)
__device__ __forceinline__ void mma_fp8(float* c, const uint32_t* a,
                                        const uint32_t* b) {
    asm volatile(
        "mma.sync.aligned.m16n8k32.row.col.f32.e4m3.e4m3.f32 "
        "{%0,%1,%2,%3}, {%4,%5,%6,%7}, {%8,%9}, {%0,%1,%2,%3};"
        : "+f"(c[0]), "+f"(c[1]), "+f"(c[2]), "+f"(c[3])
        : "r"(a[0]), "r"(a[1]), "r"(a[2]), "r"(a[3]), "r"(b[0]), "r"(b[1]));
}

__device__ __forceinline__ uint8_t fp8_byte(float v) {
    // e4m3 quantize (RN-even satfinite == ml_dtypes grid)
    return (uint8_t)__nv_cvt_float_to_fp8(v, __NV_SATFINITE, __NV_E4M3);
}

// ---------------------------------------------------------------------------
// Kernel 1: activation blockwise fp8 quantize (raw e4m3 bytes) + scale
// ---------------------------------------------------------------------------
__global__ void __launch_bounds__(256) quant_x_kernel(const float* __restrict__ x) {
    int wg = (blockIdx.x * blockDim.x + threadIdx.x) >> 5; // block index = m*32+kb
    int lane = threadIdx.x & 31;
    size_t base = (size_t)wg * QBLOCK;
    float4 v = reinterpret_cast<const float4*>(x + base)[lane];

    float amax = fmaxf(fmaxf(fabsf(v.x), fabsf(v.y)), fmaxf(fabsf(v.z), fabsf(v.w)));
    #pragma unroll
    for (int off = 16; off > 0; off >>= 1)
        amax = fmaxf(amax, __shfl_xor_sync(0xffffffffu, amax, off));
    float scale = fmaxf(amax, 1e-12f) / FP8_MAX_F;
    float inv = 1.0f / scale;

    uint32_t p = (uint32_t)fp8_byte(v.x * inv) |
                 ((uint32_t)fp8_byte(v.y * inv) << 8) |
                 ((uint32_t)fp8_byte(v.z * inv) << 16) |
                 ((uint32_t)fp8_byte(v.w * inv) << 24);
    reinterpret_cast<uint32_t*>(g_A)[(size_t)wg * 32 + lane] = p;

    if (lane == 0) g_Sx[wg] = scale;  // layout [m][kb] == linear wg
}

// ---------------------------------------------------------------------------
// Kernel 2: weight fp8 cast (raw e4m3 bytes; scales applied in GEMM)
// ---------------------------------------------------------------------------
__global__ void __launch_bounds__(256) quant_w_kernel(const float* __restrict__ w) {
    size_t i = ((size_t)blockIdx.x * blockDim.x + threadIdx.x) * 4;
    float4 v = *reinterpret_cast<const float4*>(w + i);
    uint32_t p = (uint32_t)fp8_byte(v.x) |
                 ((uint32_t)fp8_byte(v.y) << 8) |
                 ((uint32_t)fp8_byte(v.z) << 16) |
                 ((uint32_t)fp8_byte(v.w) << 24);
    reinterpret_cast<uint32_t*>(g_B)[i >> 2] = p;
}

// ---------------------------------------------------------------------------
// Kernel 3: fp8 mma.sync GEMM, Horner per-128k-block rescale
//   y[m,n] = sum_kb f(m,kb) * S_kb(m,n),  f = sx(m,kb)*sw(nb,kb)
//   Horner: acc *= f_kb/f_{kb+1} at each block boundary; *= f_31 at the end
// ---------------------------------------------------------------------------
__global__ void __launch_bounds__(256, 2) gemm_kernel(const float* __restrict__ wsinv,
                                                      const float* __restrict__ bias,
                                                      float* __restrict__ out) {
    extern __shared__ uint8_t smem[];
    __shared__ float bias_s[BN];
    __shared__ float ratio_s[KBLOCKS * BM];  // [kb][m_local], 16KB

    const int tid = threadIdx.x;
    const int wid = tid >> 5;
    const int lane = tid & 31;
    const int warp_m = wid & 1;   // 0..1 -> m rows 64*warp_m
    const int warp_n = wid >> 1;  // 0..3 -> n cols 32*warp_n

    // n-major rasterization: consecutive CTAs share the A band, B stays in L2
    const int n_tile = blockIdx.x & ((NDIM / BN) - 1);
    const int m_tile = blockIdx.x >> 5;
    const int m0 = m_tile * BM;
    const int n0 = n_tile * BN;
    const int nb = n0 >> 7;       // weight n-block (BN == QBLOCK)

    if (tid < BN)
        bias_s[tid] = __bfloat162float(__float2bfloat16_rn(bias[n0 + tid]));
    // ratio table: ratio[kb][m] = f(m,kb)/f(m,kb+1) for kb<31; ratio[31][m] = f(m,31)
    #pragma unroll
    for (int idx = tid; idx < KBLOCKS * BM; idx += 256) {
        int m = idx >> 5, kb = idx & (KBLOCKS - 1);
        const float* sxp = g_Sx + (size_t)(m0 + m) * KBLOCKS;
        float f0 = wsinv[nb * KBLOCKS + kb] * sxp[kb];
        float r;
        if (kb < KBLOCKS - 1) {
            float f1 = wsinv[nb * KBLOCKS + kb + 1] * sxp[kb + 1];
            r = f0 / f1;
        } else {
            r = f0;
        }
        ratio_s[kb * BM + m] = r;
    }
    __syncthreads();

    const uint8_t* Abase = g_A + (size_t)m0 * KDIM;
    const uint8_t* Bbase = g_B + (size_t)n0 * KDIM;
    const uint32_t smem_u32 = (uint32_t)__cvta_generic_to_shared(smem);

    auto issue_stage = [&](int kt, int s) {
        const int k0 = kt * BK;
        uint32_t a_s = smem_u32 + s * STAGE_BYTES;
        uint32_t b_s = a_s + A_BYTES;
        #pragma unroll
        for (int j = 0; j < 2; j++) {  // A: 128 rows x 4 x 16B = 512 chunks
            int c = tid + j * 256;
            int row = c >> 2, c16 = (c & 3) * 16;
            cp_async16(a_s + row * LDAB + c16,
                       Abase + (size_t)row * KDIM + k0 + c16);
        }
        #pragma unroll
        for (int j = 0; j < 2; j++) {  // B: 128 rows x 4 chunks = 512 chunks
            int c = tid + j * 256;
            int row = c >> 2, c16 = (c & 3) * 16;
            cp_async16(b_s + row * LDAB + c16,
                       Bbase + (size_t)row * KDIM + k0 + c16);
        }
        asm volatile("cp.async.commit_group;" ::: "memory");
    };

    float acc[4][4][4];   // [mf][nf][frag] — single Horner accumulator
    #pragma unroll
    for (int mf = 0; mf < 4; mf++)
        #pragma unroll
        for (int nf = 0; nf < 4; nf++)
            #pragma unroll
            for (int j = 0; j < 4; j++) acc[mf][nf][j] = 0.f;

    #pragma unroll
    for (int s = 0; s < STAGES - 1; s++) issue_stage(s, s);

    const int qrow = lane >> 2;
    const int qcol = (lane & 3) * 2;

    for (int kt = 0; kt < KTILES; kt++) {
        if (kt < KTILES - (STAGES - 1))
            asm volatile("cp.async.wait_group %0;" :: "n"(STAGES - 2) : "memory");
        else
            asm volatile("cp.async.wait_group 0;" ::: "memory");
        __syncthreads();

        int nxt = kt + STAGES - 1;
        if (nxt < KTILES) issue_stage(nxt, nxt & (STAGES - 1));

        const int s = kt & (STAGES - 1);
        const uint32_t a_s = smem_u32 + s * STAGE_BYTES;
        const uint32_t b_s = a_s + A_BYTES;

        #pragma unroll
        for (int ks = 0; ks < 2; ks++) {   // two k32 steps per BK=64
            const int kbyte = ks * 32;
            uint32_t a[4][4], b[2][4];
            #pragma unroll
            for (int mf = 0; mf < 4; mf++) {
                int row = warp_m * 64 + mf * 16 + (lane & 15);
                int byte = kbyte + (lane >> 4) * 16;
                ldmatrix_x4(a[mf], a_s + row * LDAB + byte);
            }
            #pragma unroll
            for (int p = 0; p < 2; p++) {  // paired-B x4: two n8 frags per op
                int row = warp_n * 32 + p * 16 + ((lane >> 4) * 8) + (lane & 7);
                int byte = kbyte + ((lane >> 3) & 1) * 16;
                ldmatrix_x4(b[p], b_s + row * LDAB + byte);
            }
            #pragma unroll
            for (int mf = 0; mf < 4; mf++)
                #pragma unroll
                for (int nf = 0; nf < 4; nf++)
                    mma_fp8(acc[mf][nf], a[mf], &b[nf >> 1][(nf & 1) * 2]);
        }

        if (kt & 1) {  // block boundary: Horner multiply by ratio (exact telescoping)
            const int kb = kt >> 1;
            const float* rp = ratio_s + kb * BM;
            #pragma unroll
            for (int mf = 0; mf < 4; mf++) {
                int r0 = warp_m * 64 + mf * 16 + qrow;
                float f0 = rp[r0];
                float f1 = rp[r0 + 8];
                #pragma unroll
                for (int nf = 0; nf < 4; nf++) {
                    acc[mf][nf][0] *= f0;
                    acc[mf][nf][1] *= f0;
                    acc[mf][nf][2] *= f1;
                    acc[mf][nf][3] *= f1;
                }
            }
        }
    }

    // Epilogue: bf16(y) + bf16(bias), f32 add, round to bf16, upcast to f32
    #pragma unroll
    for (int mf = 0; mf < 4; mf++) {
        #pragma unroll
        for (int nf = 0; nf < 4; nf++) {
            int cn = warp_n * 32 + nf * 8 + qcol;
            float b0 = bias_s[cn], b1 = bias_s[cn + 1];
            #pragma unroll
            for (int half = 0; half < 2; half++) {
                int m = m0 + warp_m * 64 + mf * 16 + qrow + half * 8;
                float y0 = acc[mf][nf][half * 2 + 0];
                float y1 = acc[mf][nf][half * 2 + 1];
                float v0 = __bfloat162float(__float2bfloat16_rn(y0)) + b0;
                float v1 = __bfloat162float(__float2bfloat16_rn(y1)) + b1;
                float2 o;
                o.x = __bfloat162float(__float2bfloat16_rn(v0));
                o.y = __bfloat162float(__float2bfloat16_rn(v1));
                *reinterpret_cast<float2*>(out + (size_t)m * NDIM + n0 + cn) = o;
            }
        }
    }
}

// ---------------------------------------------------------------------------
// launch — inputs resolved by element count (robust to metadata ordering)
// ---------------------------------------------------------------------------
extern "C" void kernel_launch(void* const* d_in, const int* in_sizes, int n_in,
                              void* d_out, int out_size) {
    (void)out_size;
    const float *x = nullptr, *w = nullptr, *wsinv = nullptr, *bias = nullptr;
    for (int i = 0; i < n_in; i++) {
        switch (in_sizes[i]) {
            case MDIM * KDIM:                 x     = (const float*)d_in[i]; break; // 33554432
            case NDIM * KDIM:                 w     = (const float*)d_in[i]; break; // 16777216
            case (NDIM/QBLOCK)*(KDIM/QBLOCK): wsinv = (const float*)d_in[i]; break; // 1024
            case NDIM:                        bias  = (const float*)d_in[i]; break; // 4096
        }
    }
    float* out = (float*)d_out;

    {
        int nblocks = (MDIM * KBLOCKS) / 8; // 8 warps per CTA
        quant_x_kernel<<<nblocks, 256>>>(x);
    }
    {
        int nblocks = (NDIM * KDIM) / 4 / 256;
        quant_w_kernel<<<nblocks, 256>>>(w);
    }
    {
        cudaFuncSetAttribute(gemm_kernel,
                             cudaFuncAttributeMaxDynamicSharedMemorySize, SMEM_DYN);
        dim3 grid((MDIM / BM) * (NDIM / BN));  // 2048
        gemm_kernel<<<grid, 256, SMEM_DYN>>>(wsinv, bias, out);
    }
}

// round 12
// speedup vs baseline: 1.3409x; 1.0062x over previous
#include <cuda_runtime.h>
#include <cuda_bf16.h>
#include <cuda_fp16.h>
#include <cuda_fp8.h>
#include <cstdint>
#include <cstddef>

// Problem dims (fixed by the dataset)
#define MDIM 8192
#define KDIM 4096
#define NDIM 4096
#define QBLOCK 128
#define FP8_MAX_F 448.0f
#define KBLOCKS (KDIM / QBLOCK)   // 32

// GEMM tiling: CTA 128x128x64(fp8), 8 warps as 2(m) x 4(n), warp tile 64x32
#define BM 128
#define BN 128
#define BK 64
#define KTILES (KDIM / BK)        // 64
#define STAGES 4
#define LDAB 80                   // 64B fp8 row + 16B pad (conflict-free ldmatrix)
#define A_BYTES (BM * LDAB)       // 10240
#define B_BYTES (BN * LDAB)       // 10240
#define STAGE_BYTES (A_BYTES + B_BYTES)      // 20480
#define SMEM_DYN (STAGES * STAGE_BYTES)      // 81920

// fused quant kernel split
#define QX_BLOCKS ((MDIM * KBLOCKS) / 8)       // 32768 (8 warps/CTA, warp per block)
#define QW_BLOCKS ((NDIM * KDIM) / 8 / 256)    // 8192  (8 elems/thread)

// Scratch (device globals; no runtime allocation)
__device__ __align__(16) uint8_t g_A[(size_t)MDIM * KDIM];    // 32 MB, [M][K]
__device__ __align__(16) uint8_t g_B[(size_t)NDIM * KDIM];    // 16 MB, [N][K]
__device__ __align__(16) float   g_Sx[(size_t)MDIM * KBLOCKS]; // 1 MB, [M][Kb]

// ---------------------------------------------------------------------------
// helpers
// ---------------------------------------------------------------------------
__device__ __forceinline__ void cp_async16(uint32_t smem_dst, const void* gptr) {
    asm volatile("cp.async.cg.shared.global [%0], [%1], 16;"
                 :: "r"(smem_dst), "l"(gptr) : "memory");
}

__device__ __forceinline__ void ldmatrix_x4(uint32_t* r, uint32_t addr) {
    asm volatile("ldmatrix.sync.aligned.m8n8.x4.shared.b16 {%0,%1,%2,%3}, [%4];"
                 : "=r"(r[0]), "=r"(r[1]), "=r"(r[2]), "=r"(r[3])
                 : "r"(addr) : "memory");
}

// fp8 e4m3 MMA: m16n8k32, f32 accumulate (sm_89+ baseline feature)
__device__ __forceinline__ void mma_fp8(float* c, const uint32_t* a,
                                        const uint32_t* b) {
    asm volatile(
        "mma.sync.aligned.m16n8k32.row.col.f32.e4m3.e4m3.f32 "
        "{%0,%1,%2,%3}, {%4,%5,%6,%7}, {%8,%9}, {%0,%1,%2,%3};"
        : "+f"(c[0]), "+f"(c[1]), "+f"(c[2]), "+f"(c[3])
        : "r"(a[0]), "r"(a[1]), "r"(a[2]), "r"(a[3]), "r"(b[0]), "r"(b[1]));
}

// packed e4m3x2 convert (RN, satfinite) — low byte = .x, high byte = .y
__device__ __forceinline__ uint32_t fp8x4(float a, float b, float c, float d) {
    __nv_fp8x2_storage_t lo = __nv_cvt_float2_to_fp8x2(make_float2(a, b),
                                                       __NV_SATFINITE, __NV_E4M3);
    __nv_fp8x2_storage_t hi = __nv_cvt_float2_to_fp8x2(make_float2(c, d),
                                                       __NV_SATFINITE, __NV_E4M3);
    return (uint32_t)lo | ((uint32_t)hi << 16);
}

// ---------------------------------------------------------------------------
// Kernel 1 (fused): activation blockwise fp8 quantize + weight fp8 cast
//   blocks [0, QX_BLOCKS)              -> x path (one warp per 128-elem block)
//   blocks [QX_BLOCKS, +QW_BLOCKS)     -> w path (8 elems per thread)
// ---------------------------------------------------------------------------
__global__ void __launch_bounds__(256) quant_fused_kernel(const float* __restrict__ x,
                                                          const float* __restrict__ w) {
    if (blockIdx.x < QX_BLOCKS) {
        int wg = (blockIdx.x * 256 + threadIdx.x) >> 5;  // block index = m*32+kb
        int lane = threadIdx.x & 31;
        size_t base = (size_t)wg * QBLOCK;
        float4 v = reinterpret_cast<const float4*>(x + base)[lane];

        float amax = fmaxf(fmaxf(fabsf(v.x), fabsf(v.y)),
                           fmaxf(fabsf(v.z), fabsf(v.w)));
        #pragma unroll
        for (int off = 16; off > 0; off >>= 1)
            amax = fmaxf(amax, __shfl_xor_sync(0xffffffffu, amax, off));
        float scale = fmaxf(amax, 1e-12f) / FP8_MAX_F;
        float inv = 1.0f / scale;

        uint32_t p = fp8x4(v.x * inv, v.y * inv, v.z * inv, v.w * inv);
        reinterpret_cast<uint32_t*>(g_A)[(size_t)wg * 32 + lane] = p;

        if (lane == 0) g_Sx[wg] = scale;  // layout [m][kb] == linear wg
    } else {
        size_t i = ((size_t)(blockIdx.x - QX_BLOCKS) * 256 + threadIdx.x) * 8;
        float4 v0 = *reinterpret_cast<const float4*>(w + i);
        float4 v1 = *reinterpret_cast<const float4*>(w + i + 4);
        uint2 p;
        p.x = fp8x4(v0.x, v0.y, v0.z, v0.w);
        p.y = fp8x4(v1.x, v1.y, v1.z, v1.w);
        *reinterpret_cast<uint2*>(g_B + i) = p;
    }
}

// ---------------------------------------------------------------------------
// Kernel 2: fp8 mma.sync GEMM, Horner per-128k-block rescale
//   y[m,n] = sum_kb f(m,kb) * S_kb(m,n),  f = sx(m,kb)*sw(nb,kb)
//   Horner: acc *= f_kb/f_{kb+1} at each block boundary; *= f_31 at the end
//   (unchanged from R10 — mainloop is at the legacy-mma MAC ceiling)
// ---------------------------------------------------------------------------
__global__ void __launch_bounds__(256, 2) gemm_kernel(const float* __restrict__ wsinv,
                                                      const float* __restrict__ bias,
                                                      float* __restrict__ out) {
    extern __shared__ uint8_t smem[];
    __shared__ float bias_s[BN];
    __shared__ float ratio_s[KBLOCKS * BM];  // [kb][m_local], 16KB

    const int tid = threadIdx.x;
    const int wid = tid >> 5;
    const int lane = tid & 31;
    const int warp_m = wid & 1;   // 0..1 -> m rows 64*warp_m
    const int warp_n = wid >> 1;  // 0..3 -> n cols 32*warp_n

    // n-major rasterization: consecutive CTAs share the A band, B stays in L2
    const int n_tile = blockIdx.x & ((NDIM / BN) - 1);
    const int m_tile = blockIdx.x >> 5;
    const int m0 = m_tile * BM;
    const int n0 = n_tile * BN;
    const int nb = n0 >> 7;       // weight n-block (BN == QBLOCK)

    if (tid < BN)
        bias_s[tid] = __bfloat162float(__float2bfloat16_rn(bias[n0 + tid]));
    // ratio table: ratio[kb][m] = f(m,kb)/f(m,kb+1) for kb<31; ratio[31][m] = f(m,31)
    #pragma unroll
    for (int idx = tid; idx < KBLOCKS * BM; idx += 256) {
        int m = idx >> 5, kb = idx & (KBLOCKS - 1);
        const float* sxp = g_Sx + (size_t)(m0 + m) * KBLOCKS;
        float f0 = wsinv[nb * KBLOCKS + kb] * sxp[kb];
        float r;
        if (kb < KBLOCKS - 1) {
            float f1 = wsinv[nb * KBLOCKS + kb + 1] * sxp[kb + 1];
            r = f0 / f1;
        } else {
            r = f0;
        }
        ratio_s[kb * BM + m] = r;
    }
    __syncthreads();

    const uint8_t* Abase = g_A + (size_t)m0 * KDIM;
    const uint8_t* Bbase = g_B + (size_t)n0 * KDIM;
    const uint32_t smem_u32 = (uint32_t)__cvta_generic_to_shared(smem);

    auto issue_stage = [&](int kt, int s) {
        const int k0 = kt * BK;
        uint32_t a_s = smem_u32 + s * STAGE_BYTES;
        uint32_t b_s = a_s + A_BYTES;
        #pragma unroll
        for (int j = 0; j < 2; j++) {  // A: 128 rows x 4 x 16B = 512 chunks
            int c = tid + j * 256;
            int row = c >> 2, c16 = (c & 3) * 16;
            cp_async16(a_s + row * LDAB + c16,
                       Abase + (size_t)row * KDIM + k0 + c16);
        }
        #pragma unroll
        for (int j = 0; j < 2; j++) {  // B: 128 rows x 4 chunks = 512 chunks
            int c = tid + j * 256;
            int row = c >> 2, c16 = (c & 3) * 16;
            cp_async16(b_s + row * LDAB + c16,
                       Bbase + (size_t)row * KDIM + k0 + c16);
        }
        asm volatile("cp.async.commit_group;" ::: "memory");
    };

    float acc[4][4][4];   // [mf][nf][frag] — single Horner accumulator
    #pragma unroll
    for (int mf = 0; mf < 4; mf++)
        #pragma unroll
        for (int nf = 0; nf < 4; nf++)
            #pragma unroll
            for (int j = 0; j < 4; j++) acc[mf][nf][j] = 0.f;

    #pragma unroll
    for (int s = 0; s < STAGES - 1; s++) issue_stage(s, s);

    const int qrow = lane >> 2;
    const int qcol = (lane & 3) * 2;

    for (int kt = 0; kt < KTILES; kt++) {
        if (kt < KTILES - (STAGES - 1))
            asm volatile("cp.async.wait_group %0;" :: "n"(STAGES - 2) : "memory");
        else
            asm volatile("cp.async.wait_group 0;" ::: "memory");
        __syncthreads();

        int nxt = kt + STAGES - 1;
        if (nxt < KTILES) issue_stage(nxt, nxt & (STAGES - 1));

        const int s = kt & (STAGES - 1);
        const uint32_t a_s = smem_u32 + s * STAGE_BYTES;
        const uint32_t b_s = a_s + A_BYTES;

        #pragma unroll
        for (int ks = 0; ks < 2; ks++) {   // two k32 steps per BK=64
            const int kbyte = ks * 32;
            uint32_t a[4][4], b[2][4];
            #pragma unroll
            for (int mf = 0; mf < 4; mf++) {
                int row = warp_m * 64 + mf * 16 + (lane & 15);
                int byte = kbyte + (lane >> 4) * 16;
                ldmatrix_x4(a[mf], a_s + row * LDAB + byte);
            }
            #pragma unroll
            for (int p = 0; p < 2; p++) {  // paired-B x4: two n8 frags per op
                int row = warp_n * 32 + p * 16 + ((lane >> 4) * 8) + (lane & 7);
                int byte = kbyte + ((lane >> 3) & 1) * 16;
                ldmatrix_x4(b[p], b_s + row * LDAB + byte);
            }
            #pragma unroll
            for (int mf = 0; mf < 4; mf++)
                #pragma unroll
                for (int nf = 0; nf < 4; nf++)
                    mma_fp8(acc[mf][nf], a[mf], &b[nf >> 1][(nf & 1) * 2]);
        }

        if (kt & 1) {  // block boundary: Horner multiply by ratio (exact telescoping)
            const int kb = kt >> 1;
            const float* rp = ratio_s + kb * BM;
            #pragma unroll
            for (int mf = 0; mf < 4; mf++) {
                int r0 = warp_m * 64 + mf * 16 + qrow;
                float f0 = rp[r0];
                float f1 = rp[r0 + 8];
                #pragma unroll
                for (int nf = 0; nf < 4; nf++) {
                    acc[mf][nf][0] *= f0;
                    acc[mf][nf][1] *= f0;
                    acc[mf][nf][2] *= f1;
                    acc[mf][nf][3] *= f1;
                }
            }
        }
    }

    // Epilogue: bf16(y) + bf16(bias), f32 add, round to bf16, upcast to f32
    #pragma unroll
    for (int mf = 0; mf < 4; mf++) {
        #pragma unroll
        for (int nf = 0; nf < 4; nf++) {
            int cn = warp_n * 32 + nf * 8 + qcol;
            float b0 = bias_s[cn], b1 = bias_s[cn + 1];
            #pragma unroll
            for (int half = 0; half < 2; half++) {
                int m = m0 + warp_m * 64 + mf * 16 + qrow + half * 8;
                float y0 = acc[mf][nf][half * 2 + 0];
                float y1 = acc[mf][nf][half * 2 + 1];
                float v0 = __bfloat162float(__float2bfloat16_rn(y0)) + b0;
                float v1 = __bfloat162float(__float2bfloat16_rn(y1)) + b1;
                float2 o;
                o.x = __bfloat162float(__float2bfloat16_rn(v0));
                o.y = __bfloat162float(__float2bfloat16_rn(v1));
                *reinterpret_cast<float2*>(out + (size_t)m * NDIM + n0 + cn) = o;
            }
        }
    }
}

// ---------------------------------------------------------------------------
// launch — inputs resolved by element count (robust to metadata ordering)
// ---------------------------------------------------------------------------
extern "C" void kernel_launch(void* const* d_in, const int* in_sizes, int n_in,
                              void* d_out, int out_size) {
    (void)out_size;
    const float *x = nullptr, *w = nullptr, *wsinv = nullptr, *bias = nullptr;
    for (int i = 0; i < n_in; i++) {
        switch (in_sizes[i]) {
            case MDIM * KDIM:                 x     = (const float*)d_in[i]; break; // 33554432
            case NDIM * KDIM:                 w     = (const float*)d_in[i]; break; // 16777216
            case (NDIM/QBLOCK)*(KDIM/QBLOCK): wsinv = (const float*)d_in[i]; break; // 1024
            case NDIM:                        bias  = (const float*)d_in[i]; break; // 4096
        }
    }
    float* out = (float*)d_out;

    {
        quant_fused_kernel<<<QX_BLOCKS + QW_BLOCKS, 256>>>(x, w);
    }
    {
        cudaFuncSetAttribute(gemm_kernel,
                             cudaFuncAttributeMaxDynamicSharedMemorySize, SMEM_DYN);
        dim3 grid((MDIM / BM) * (NDIM / BN));  // 2048
        gemm_kernel<<<grid, 256, SMEM_DYN>>>(wsinv, bias, out);
    }
}

// round 14
// speedup vs baseline: 1.4356x; 1.0707x over previous
#include <cuda_runtime.h>
#include <cuda_bf16.h>
#include <cuda_fp16.h>
#include <cuda_fp8.h>
#include <cstdint>
#include <cstddef>

// Problem dims (fixed by the dataset)
#define MDIM 8192
#define KDIM 4096
#define NDIM 4096
#define QBLOCK 128
#define FP8_MAX_F 448.0f
#define KBLOCKS (KDIM / QBLOCK)   // 32

// GEMM tiling: CTA 128x128x64(fp8), 8 warps as 2(m) x 4(n), warp tile 64x32
#define BM 128
#define BN 128
#define BK 64
#define KTILES (KDIM / BK)        // 64
#define STAGES 4
#define LDAB 80                   // 64B fp8 row + 16B pad (conflict-free ldmatrix)
#define A_BYTES (BM * LDAB)       // 10240
#define B_BYTES (BN * LDAB)       // 10240
#define STAGE_BYTES (A_BYTES + B_BYTES)      // 20480
#define SMEM_DYN (STAGES * STAGE_BYTES)      // 81920

// fused quant kernel split
#define QX_BLOCKS ((MDIM * KBLOCKS) / 8)       // 32768 (8 warps/CTA, warp per block)
#define QW_BLOCKS ((NDIM * KDIM) / 8 / 256)    // 8192  (8 elems/thread)

// Scratch (device globals; no runtime allocation)
__device__ __align__(16) uint8_t g_A[(size_t)MDIM * KDIM];    // 32 MB, [M][K]
__device__ __align__(16) uint8_t g_B[(size_t)NDIM * KDIM];    // 16 MB, [N][K]
__device__ __align__(16) float   g_Sx[(size_t)MDIM * KBLOCKS]; // 1 MB, [M][Kb]

// ---------------------------------------------------------------------------
// helpers
// ---------------------------------------------------------------------------
__device__ __forceinline__ void cp_async16(uint32_t smem_dst, const void* gptr) {
    asm volatile("cp.async.cg.shared.global [%0], [%1], 16;"
                 :: "r"(smem_dst), "l"(gptr) : "memory");
}

__device__ __forceinline__ void ldmatrix_x4(uint32_t* r, uint32_t addr) {
    asm volatile("ldmatrix.sync.aligned.m8n8.x4.shared.b16 {%0,%1,%2,%3}, [%4];"
                 : "=r"(r[0]), "=r"(r[1]), "=r"(r[2]), "=r"(r[3])
                 : "r"(addr) : "memory");
}

// fp8 e4m3 MMA: m16n8k32, f32 accumulate (sm_89+ baseline feature)
__device__ __forceinline__ void mma_fp8(float* c, const uint32_t* a,
                                        const uint32_t* b) {
    asm volatile(
        "mma.sync.aligned.m16n8k32.row.col.f32.e4m3.e4m3.f32 "
        "{%0,%1,%2,%3}, {%4,%5,%6,%7}, {%8,%9}, {%0,%1,%2,%3};"
        : "+f"(c[0]), "+f"(c[1]), "+f"(c[2]), "+f"(c[3])
        : "r"(a[0]), "r"(a[1]), "r"(a[2]), "r"(a[3]), "r"(b[0]), "r"(b[1]));
}

// packed e4m3x2 convert (RN, satfinite) — low byte = .x, high byte = .y
__device__ __forceinline__ uint32_t fp8x4(float a, float b, float c, float d) {
    __nv_fp8x2_storage_t lo = __nv_cvt_float2_to_fp8x2(make_float2(a, b),
                                                       __NV_SATFINITE, __NV_E4M3);
    __nv_fp8x2_storage_t hi = __nv_cvt_float2_to_fp8x2(make_float2(c, d),
                                                       __NV_SATFINITE, __NV_E4M3);
    return (uint32_t)lo | ((uint32_t)hi << 16);
}

// ---------------------------------------------------------------------------
// Kernel 1 (fused): activation blockwise fp8 quantize + weight fp8 cast
// ---------------------------------------------------------------------------
__global__ void __launch_bounds__(256) quant_fused_kernel(const float* __restrict__ x,
                                                          const float* __restrict__ w) {
    if (blockIdx.x < QX_BLOCKS) {
        int wg = (blockIdx.x * 256 + threadIdx.x) >> 5;  // block index = m*32+kb
        int lane = threadIdx.x & 31;
        size_t base = (size_t)wg * QBLOCK;
        float4 v = reinterpret_cast<const float4*>(x + base)[lane];

        float amax = fmaxf(fmaxf(fabsf(v.x), fabsf(v.y)),
                           fmaxf(fabsf(v.z), fabsf(v.w)));
        #pragma unroll
        for (int off = 16; off > 0; off >>= 1)
            amax = fmaxf(amax, __shfl_xor_sync(0xffffffffu, amax, off));
        float scale = fmaxf(amax, 1e-12f) / FP8_MAX_F;
        float inv = 1.0f / scale;

        uint32_t p = fp8x4(v.x * inv, v.y * inv, v.z * inv, v.w * inv);
        reinterpret_cast<uint32_t*>(g_A)[(size_t)wg * 32 + lane] = p;

        if (lane == 0) g_Sx[wg] = scale;  // layout [m][kb] == linear wg
    } else {
        size_t i = ((size_t)(blockIdx.x - QX_BLOCKS) * 256 + threadIdx.x) * 8;
        float4 v0 = *reinterpret_cast<const float4*>(w + i);
        float4 v1 = *reinterpret_cast<const float4*>(w + i + 4);
        uint2 p;
        p.x = fp8x4(v0.x, v0.y, v0.z, v0.w);
        p.y = fp8x4(v1.x, v1.y, v1.z, v1.w);
        *reinterpret_cast<uint2*>(g_B + i) = p;
    }
}

// ---------------------------------------------------------------------------
// Kernel 2: fp8 mma.sync GEMM, Horner per-128k-block rescale
//   kt loop unrolled by STAGES -> compile-time stage bases, hoisted addresses
// ---------------------------------------------------------------------------
__global__ void __launch_bounds__(256, 2) gemm_kernel(const float* __restrict__ wsinv,
                                                      const float* __restrict__ bias,
                                                      float* __restrict__ out) {
    extern __shared__ uint8_t smem[];
    __shared__ float bias_s[BN];
    __shared__ float ratio_s[KBLOCKS * BM];  // [kb][m_local], 16KB

    const int tid = threadIdx.x;
    const int wid = tid >> 5;
    const int lane = tid & 31;
    const int warp_m = wid & 1;   // 0..1 -> m rows 64*warp_m
    const int warp_n = wid >> 1;  // 0..3 -> n cols 32*warp_n

    // n-major rasterization: consecutive CTAs share the A band, B stays in L2
    const int n_tile = blockIdx.x & ((NDIM / BN) - 1);
    const int m_tile = blockIdx.x >> 5;
    const int m0 = m_tile * BM;
    const int n0 = n_tile * BN;
    const int nb = n0 >> 7;       // weight n-block (BN == QBLOCK)

    if (tid < BN)
        bias_s[tid] = __bfloat162float(__float2bfloat16_rn(bias[n0 + tid]));
    // ratio table: ratio[kb][m] = f(m,kb)/f(m,kb+1) for kb<31; ratio[31][m] = f(m,31)
    #pragma unroll
    for (int idx = tid; idx < KBLOCKS * BM; idx += 256) {
        int m = idx >> 5, kb = idx & (KBLOCKS - 1);
        const float* sxp = g_Sx + (size_t)(m0 + m) * KBLOCKS;
        float f0 = wsinv[nb * KBLOCKS + kb] * sxp[kb];
        float r;
        if (kb < KBLOCKS - 1) {
            float f1 = wsinv[nb * KBLOCKS + kb + 1] * sxp[kb + 1];
            r = f0 / f1;
        } else {
            r = f0;
        }
        ratio_s[kb * BM + m] = r;
    }
    __syncthreads();

    const uint32_t smem_u32 = (uint32_t)__cvta_generic_to_shared(smem);

    // ---- precomputed cp.async running pointers + fixed smem offsets ----
    const int cp_row0 = tid >> 2;               // chunk 0 row
    const int cp_row1 = (tid + 256) >> 2;       // chunk 1 row
    const int cp_c0 = (tid & 3) * 16;
    const uint32_t aSm0 = cp_row0 * LDAB + cp_c0;
    const uint32_t aSm1 = cp_row1 * LDAB + cp_c0;
    const uint32_t bSm0 = A_BYTES + aSm0;
    const uint32_t bSm1 = A_BYTES + aSm1;
    const uint8_t* aG0 = g_A + (size_t)(m0 + cp_row0) * KDIM + cp_c0;
    const uint8_t* aG1 = g_A + (size_t)(m0 + cp_row1) * KDIM + cp_c0;
    const uint8_t* bG0 = g_B + (size_t)(n0 + cp_row0) * KDIM + cp_c0;
    const uint8_t* bG1 = g_B + (size_t)(n0 + cp_row1) * KDIM + cp_c0;

    auto issue_stage = [&](uint32_t stage_base) {
        cp_async16(stage_base + aSm0, aG0);
        cp_async16(stage_base + aSm1, aG1);
        cp_async16(stage_base + bSm0, bG0);
        cp_async16(stage_base + bSm1, bG1);
        asm volatile("cp.async.commit_group;" ::: "memory");
        aG0 += BK; aG1 += BK; bG0 += BK; bG1 += BK;
    };

    // ---- precomputed ldmatrix offsets (stage-relative) ----
    uint32_t aOff[4], bOff[2];
    #pragma unroll
    for (int mf = 0; mf < 4; mf++)
        aOff[mf] = (uint32_t)((warp_m * 64 + mf * 16 + (lane & 15)) * LDAB +
                              (lane >> 4) * 16);
    #pragma unroll
    for (int p = 0; p < 2; p++)
        bOff[p] = (uint32_t)(A_BYTES +
                             (warp_n * 32 + p * 16 + (lane >> 4) * 8 + (lane & 7)) * LDAB +
                             ((lane >> 3) & 1) * 16);

    float acc[4][4][4];   // [mf][nf][frag] — single Horner accumulator
    #pragma unroll
    for (int mf = 0; mf < 4; mf++)
        #pragma unroll
        for (int nf = 0; nf < 4; nf++)
            #pragma unroll
            for (int j = 0; j < 4; j++) acc[mf][nf][j] = 0.f;

    issue_stage(smem_u32 + 0 * STAGE_BYTES);
    issue_stage(smem_u32 + 1 * STAGE_BYTES);
    issue_stage(smem_u32 + 2 * STAGE_BYTES);

    const int qrow = lane >> 2;
    const int qcol = (lane & 3) * 2;
    int rBase[4];
    #pragma unroll
    for (int mf = 0; mf < 4; mf++) rBase[mf] = warp_m * 64 + mf * 16 + qrow;

    const float* rp = ratio_s;   // advances BM per 128-k block boundary

    for (int kt0 = 0; kt0 < KTILES; kt0 += STAGES) {
        #pragma unroll
        for (int s = 0; s < STAGES; s++) {
            const int kt = kt0 + s;
            if (kt < KTILES - (STAGES - 1))
                asm volatile("cp.async.wait_group %0;" :: "n"(STAGES - 2) : "memory");
            else
                asm volatile("cp.async.wait_group 0;" ::: "memory");
            __syncthreads();

            if (kt + STAGES - 1 < KTILES)
                issue_stage(smem_u32 + ((s + STAGES - 1) & (STAGES - 1)) * STAGE_BYTES);

            const uint32_t stage_base = smem_u32 + s * STAGE_BYTES;

            #pragma unroll
            for (int ks = 0; ks < 2; ks++) {   // two k32 steps per BK=64
                const uint32_t kbyte = ks * 32;
                uint32_t a[4][4], b[2][4];
                #pragma unroll
                for (int mf = 0; mf < 4; mf++)
                    ldmatrix_x4(a[mf], stage_base + aOff[mf] + kbyte);
                #pragma unroll
                for (int p = 0; p < 2; p++)
                    ldmatrix_x4(b[p], stage_base + bOff[p] + kbyte);
                #pragma unroll
                for (int mf = 0; mf < 4; mf++)
                    #pragma unroll
                    for (int nf = 0; nf < 4; nf++)
                        mma_fp8(acc[mf][nf], a[mf], &b[nf >> 1][(nf & 1) * 2]);
            }

            if (s & 1) {  // kt odd: block boundary — Horner multiply (telescoping)
                #pragma unroll
                for (int mf = 0; mf < 4; mf++) {
                    float f0 = rp[rBase[mf]];
                    float f1 = rp[rBase[mf] + 8];
                    #pragma unroll
                    for (int nf = 0; nf < 4; nf++) {
                        acc[mf][nf][0] *= f0;
                        acc[mf][nf][1] *= f0;
                        acc[mf][nf][2] *= f1;
                        acc[mf][nf][3] *= f1;
                    }
                }
                rp += BM;
            }
        }
    }

    // Epilogue: bf16(y) + bf16(bias), f32 add, round to bf16, upcast to f32
    #pragma unroll
    for (int mf = 0; mf < 4; mf++) {
        #pragma unroll
        for (int nf = 0; nf < 4; nf++) {
            int cn = warp_n * 32 + nf * 8 + qcol;
            float b0 = bias_s[cn], b1 = bias_s[cn + 1];
            #pragma unroll
            for (int half = 0; half < 2; half++) {
                int m = m0 + warp_m * 64 + mf * 16 + qrow + half * 8;
                float y0 = acc[mf][nf][half * 2 + 0];
                float y1 = acc[mf][nf][half * 2 + 1];
                float v0 = __bfloat162float(__float2bfloat16_rn(y0)) + b0;
                float v1 = __bfloat162float(__float2bfloat16_rn(y1)) + b1;
                float2 o;
                o.x = __bfloat162float(__float2bfloat16_rn(v0));
                o.y = __bfloat162float(__float2bfloat16_rn(v1));
                *reinterpret_cast<float2*>(out + (size_t)m * NDIM + n0 + cn) = o;
            }
        }
    }
}

// ---------------------------------------------------------------------------
// launch — inputs resolved by element count (robust to metadata ordering)
// ---------------------------------------------------------------------------
extern "C" void kernel_launch(void* const* d_in, const int* in_sizes, int n_in,
                              void* d_out, int out_size) {
    (void)out_size;
    const float *x = nullptr, *w = nullptr, *wsinv = nullptr, *bias = nullptr;
    for (int i = 0; i < n_in; i++) {
        switch (in_sizes[i]) {
            case MDIM * KDIM:                 x     = (const float*)d_in[i]; break; // 33554432
            case NDIM * KDIM:                 w     = (const float*)d_in[i]; break; // 16777216
            case (NDIM/QBLOCK)*(KDIM/QBLOCK): wsinv = (const float*)d_in[i]; break; // 1024
            case NDIM:                        bias  = (const float*)d_in[i]; break; // 4096
        }
    }
    float* out = (float*)d_out;

    {
        quant_fused_kernel<<<QX_BLOCKS + QW_BLOCKS, 256>>>(x, w);
    }
    {
        cudaFuncSetAttribute(gemm_kernel,
                             cudaFuncAttributeMaxDynamicSharedMemorySize, SMEM_DYN);
        dim3 grid((MDIM / BM) * (NDIM / BN));  // 2048
        gemm_kernel<<<grid, 256, SMEM_DYN>>>(wsinv, bias, out);
    }
}